// round 13
// baseline (speedup 1.0000x reference)
#include <cuda_runtime.h>
#include <cuda_bf16.h>
#include <math.h>
#include <stdint.h>

#define BATCH 500
#define BPAD 512
#define TSTEPS 256
#define EMB 512
#define HID 512
#define NOUT 100
#define TBSTRIDE (TSTEPS * EMB)
#define MROWS (TSTEPS * BPAD)

// ------------------------- device globals (scratch) -------------------------
__device__ __nv_bfloat16 g_xbf[(size_t)MROWS * EMB];        // 134MB  [t*512+b][e]
__device__ __nv_bfloat16 g_Wx[2048 * 512];
__device__ __nv_bfloat16 g_Wh[2048 * 512];
__device__ __nv_bfloat16 g_Wf[128 * 512];
__device__ float g_pb[2048];
__device__ __nv_bfloat16 g_xg[(size_t)MROWS * 2048];        // 540MB xg bf16
__device__ __nv_bfloat16 g_hb[(size_t)TSTEPS * BPAD * HID]; // 134MB bf16 h, t-indexed
// per-CTA flags: [mgroup 0..3][ctaY 0..31], each slot padded to 128B (32 u32)
__device__ unsigned g_flag[4 * 32 * 32];

__device__ __forceinline__ float fast_sigmoid(float x) {
    return 1.f / (1.f + __expf(-x));
}
__device__ __forceinline__ float fast_tanh(float x) {
    float ax = fabsf(x);
    float e = __expf(-2.f * ax);
    float r = (1.f - e) / (1.f + e);
    return copysignf(r, x);
}

// ------------------------- init / prep -------------------------
__global__ void zero_state_kernel() {
    int idx = blockIdx.x * blockDim.x + threadIdx.x;
    if (idx < 4 * 32 * 32) g_flag[idx] = 0u;
}

__global__ void prep_xbf_kernel(const float* __restrict__ inp) {
    long long idx = (long long)blockIdx.x * blockDim.x + threadIdx.x;
    if (idx >= (long long)TSTEPS * BATCH * EMB) return;
    int e = (int)(idx & 511);
    long long r = idx >> 9;
    int b = (int)(r % BATCH);
    int t = (int)(r / BATCH);
    float v = inp[(size_t)b * TBSTRIDE + (size_t)t * EMB + e];
    g_xbf[((size_t)t * BPAD + b) * EMB + e] = __float2bfloat16_rn(v);
}

__global__ void zero_xbf_pad_kernel() {
    int idx = blockIdx.x * blockDim.x + threadIdx.x;
    int total = TSTEPS * 12 * EMB / 2;
    if (idx >= total) return;
    int per_t = 12 * EMB / 2;
    int t = idx / per_t;
    int o = idx - t * per_t;
    ((uint32_t*)(g_xbf + ((size_t)t * BPAD + BATCH) * EMB))[o] = 0u;
}

__global__ void prep_w_kernel(const float* __restrict__ Wih,
                              const float* __restrict__ Whh,
                              const float* __restrict__ bih,
                              const float* __restrict__ bhh,
                              const float* __restrict__ Wfc) {
    int idx = blockIdx.x * blockDim.x + threadIdx.x;
    int np = idx >> 10;
    int k  = idx & 1023;
    int j = np >> 2, gate = np & 3;
    int n = gate * HID + j;
    if (k < 512) g_Wx[np * 512 + k] = __float2bfloat16_rn(Wih[(size_t)n * EMB + k]);
    else         g_Wh[np * 512 + (k - 512)] = __float2bfloat16_rn(Whh[(size_t)n * HID + (k - 512)]);
    if (idx < 2048) {
        int jj = idx >> 2, gg = idx & 3;
        g_pb[idx] = bih[gg * HID + jj] + bhh[gg * HID + jj];
    }
    if (idx < 128 * 512) {
        int fn = idx >> 9, fk = idx & 511;
        g_Wf[idx] = (fn < NOUT) ? __float2bfloat16_rn(Wfc[(size_t)fn * 512 + fk])
                                : __float2bfloat16_rn(0.f);
    }
}

// ------------------------- mma / ldmatrix helpers -------------------------
__device__ __forceinline__ void mma_bf16(float* d, const uint32_t* a, const uint32_t* b) {
    asm volatile(
        "mma.sync.aligned.m16n8k16.row.col.f32.bf16.bf16.f32 "
        "{%0,%1,%2,%3}, {%4,%5,%6,%7}, {%8,%9}, {%0,%1,%2,%3};"
        : "+f"(d[0]), "+f"(d[1]), "+f"(d[2]), "+f"(d[3])
        : "r"(a[0]), "r"(a[1]), "r"(a[2]), "r"(a[3]), "r"(b[0]), "r"(b[1]));
}
__device__ __forceinline__ void ldsm_x4(uint32_t* r, uint32_t addr) {
    asm volatile("ldmatrix.sync.aligned.m8n8.x4.shared.b16 {%0,%1,%2,%3}, [%4];"
                 : "=r"(r[0]), "=r"(r[1]), "=r"(r[2]), "=r"(r[3]) : "r"(addr));
}

// -------------------------------------------------------------------------
// Big parallel GEMM: g_xg[131072][2048](bf16) = g_xbf @ g_Wx^T
// grid (16 n-tiles, 1024 m-tiles): n fastest -> A tile L2 reuse across wave.
// -------------------------------------------------------------------------
#define XS2 72
#define XBUF (128 * XS2)
#define XG_SMEM (4 * XBUF * 2)       // 73728

__global__ __launch_bounds__(256) void xg_gemm_kernel() {
    extern __shared__ __nv_bfloat16 xsm[];
    __nv_bfloat16* As = xsm;
    __nv_bfloat16* Bs = xsm + 2 * XBUF;
    const int tid = threadIdx.x;
    const int lid = tid & 31, wid = tid >> 5;
    const int tg = lid & 3, gr = lid >> 2;
    const int mw = wid & 3, nw = wid >> 2;
    const size_t R0 = (size_t)blockIdx.y * 128;
    const int n0 = blockIdx.x * 128;

    float acc[2][8][4];
#pragma unroll
    for (int mf = 0; mf < 2; mf++)
#pragma unroll
        for (int nf = 0; nf < 8; nf++)
#pragma unroll
            for (int r = 0; r < 4; r++) acc[mf][nf][r] = 0.f;

    uint32_t aA[2][2], bB[2][4];
    {
        const uint32_t abase = (uint32_t)__cvta_generic_to_shared(As);
        const uint32_t bbase = (uint32_t)__cvta_generic_to_shared(Bs);
        const int arow = mw * 32 + (lid & 15);
        const int acol = (lid >> 4) << 3;
        const int brb = nw * 64 + ((lid >> 4) << 3) + (lid & 7);
        const int bcol = ((lid >> 3) & 1) << 3;
#pragma unroll
        for (int buf = 0; buf < 2; buf++) {
#pragma unroll
            for (int mf = 0; mf < 2; mf++)
                aA[buf][mf] = abase + (uint32_t)(buf * XBUF + (arow + mf * 16) * XS2 + acol) * 2;
#pragma unroll
            for (int p = 0; p < 4; p++)
                bB[buf][p] = bbase + (uint32_t)(buf * XBUF + (brb + p * 16) * XS2 + bcol) * 2;
        }
    }

    auto load_stage = [&](int s) {
        const int buf = s & 1;
        const int k0 = s * 64;
#pragma unroll
        for (int it = 0; it < 4; it++) {
            int idx = tid + 256 * it;
            int r = idx >> 3, ch = idx & 7;
            const __nv_bfloat16* src = g_xbf + (R0 + r) * EMB + k0 + ch * 8;
            uint32_t dst = (uint32_t)__cvta_generic_to_shared(&As[buf * XBUF + r * XS2 + ch * 8]);
            asm volatile("cp.async.cg.shared.global [%0], [%1], 16;" :: "r"(dst), "l"(src));
        }
#pragma unroll
        for (int it = 0; it < 4; it++) {
            int idx = tid + 256 * it;
            int r = idx >> 3, ch = idx & 7;
            const __nv_bfloat16* src = g_Wx + (size_t)(n0 + r) * 512 + k0 + ch * 8;
            uint32_t dst = (uint32_t)__cvta_generic_to_shared(&Bs[buf * XBUF + r * XS2 + ch * 8]);
            asm volatile("cp.async.cg.shared.global [%0], [%1], 16;" :: "r"(dst), "l"(src));
        }
        asm volatile("cp.async.commit_group;" ::: "memory");
    };

    load_stage(0);
#pragma unroll 1
    for (int s = 0; s < 8; s++) {
        if (s + 1 < 8) {
            load_stage(s + 1);
            asm volatile("cp.async.wait_group 1;" ::: "memory");
        } else {
            asm volatile("cp.async.wait_group 0;" ::: "memory");
        }
        __syncthreads();
        const int buf = s & 1;
#pragma unroll
        for (int kk = 0; kk < 4; kk++) {
            uint32_t a0[4], a1[4];
            ldsm_x4(a0, aA[buf][0] + kk * 32);
            ldsm_x4(a1, aA[buf][1] + kk * 32);
#pragma unroll
            for (int p = 0; p < 4; p++) {
                uint32_t bb[4];
                ldsm_x4(bb, bB[buf][p] + kk * 32);
                mma_bf16(acc[0][2 * p],     a0, bb);
                mma_bf16(acc[0][2 * p + 1], a0, bb + 2);
                mma_bf16(acc[1][2 * p],     a1, bb);
                mma_bf16(acc[1][2 * p + 1], a1, bb + 2);
            }
        }
        __syncthreads();
    }

    uint32_t* xg32 = (uint32_t*)g_xg;
#pragma unroll
    for (int mf = 0; mf < 2; mf++)
#pragma unroll
        for (int nf = 0; nf < 8; nf++) {
            size_t R = R0 + mw * 32 + mf * 16 + gr;
            int c = n0 + nw * 64 + nf * 8 + 2 * tg;
            __nv_bfloat162 lo = __float22bfloat162_rn(make_float2(acc[mf][nf][0], acc[mf][nf][1]));
            __nv_bfloat162 hi = __float22bfloat162_rn(make_float2(acc[mf][nf][2], acc[mf][nf][3]));
            xg32[R * 1024 + (c >> 1)]       = *(uint32_t*)&lo;
            xg32[(R + 8) * 1024 + (c >> 1)] = *(uint32_t*)&hi;
        }
}

// -------------------------------------------------------------------------
// Persistent LSTM (H-GEMM only): 128 CTAs (4 m-groups x 32 n-tiles).
// Per-CTA release flags (padded, no atomics); lane-per-slot acquire spin.
// -------------------------------------------------------------------------
#define ST 520
#define HS2 24
#define OFF_WH 0
#define OFF_A  (64 * ST * 2)                    // 66560
#define OFF_HS (OFF_A + 128 * ST * 2)           // 199680
#define PERSIST_SMEM (OFF_HS + 128 * HS2 * 2)   // 205824

__global__ __launch_bounds__(256) void lstm_persist_kernel() {
    extern __shared__ char sm[];
    __nv_bfloat16* Hsb = (__nv_bfloat16*)(sm + OFF_HS);

    const int tid = threadIdx.x;
    const int lid = tid & 31, wid = tid >> 5;
    const int tg = lid & 3, gr = lid >> 2;
    const int mw = wid & 3, nw = wid >> 2;
    const int mblk = blockIdx.x;
    const int m0 = mblk * 128;
    const int n0 = blockIdx.y * 64;
    const bool even = (tg & 1) == 0;

    // my slot (writer) and my polled slot (one per lane)
    unsigned* my_flag   = &g_flag[(mblk * 32 + (int)blockIdx.y) * 32];
    const unsigned* poll_flag = &g_flag[(mblk * 32 + lid) * 32];

    // ---- Wh slice (64 rows x 512 bf16) resident ----
#pragma unroll
    for (int it = 0; it < 16; it++) {
        int idx = tid + 256 * it;
        int r = idx >> 6, ch = idx & 63;
        const __nv_bfloat16* src = g_Wh + (size_t)(n0 + r) * 512 + ch * 8;
        uint32_t dst = (uint32_t)__cvta_generic_to_shared(sm + OFF_WH + (r * ST + ch * 8) * 2);
        asm volatile("cp.async.cg.shared.global [%0], [%1], 16;" :: "r"(dst), "l"(src));
    }
    asm volatile("cp.async.commit_group;" ::: "memory");
    asm volatile("cp.async.wait_group 0;" ::: "memory");
    __syncthreads();

    uint32_t aaddr[2], baddr[2];
    {
        const uint32_t smbase = (uint32_t)__cvta_generic_to_shared(sm);
        const int arow = mw * 32 + (lid & 15);
        const int acol = (lid >> 4) << 3;
#pragma unroll
        for (int mf = 0; mf < 2; mf++)
            aaddr[mf] = smbase + OFF_A + (uint32_t)((arow + mf * 16) * ST + acol) * 2;
        const int brow = nw * 32 + ((lid >> 4) << 3) + (lid & 7);
        const int bcol = ((lid >> 3) & 1) << 3;
#pragma unroll
        for (int p = 0; p < 2; p++)
            baddr[p] = smbase + OFF_WH + (uint32_t)((brow + p * 16) * ST + bcol) * 2;
    }

    float4 pb4[4];
#pragma unroll
    for (int nf = 0; nf < 4; nf++) {
        int jc = nw * 8 + 2 * nf + (tg >> 1);
        pb4[nf] = *(const float4*)&g_pb[n0 + jc * 4];
    }

    float creg[2][4][2];
#pragma unroll
    for (int mf = 0; mf < 2; mf++)
#pragma unroll
        for (int nf = 0; nf < 4; nf++) { creg[mf][nf][0] = 0.f; creg[mf][nf][1] = 0.f; }

    const uint32_t* xg32 = (const uint32_t*)g_xg;
    const int colu = (n0 + nw * 32 + 2 * tg) >> 1;

    float acc[2][4][4];

    // quarter loader: 128 rows x 128 bf16 cols = 2048 x 16B chunks
    auto load_q = [&](const __nv_bfloat16* hsrc, int q) {
#pragma unroll
        for (int it = 0; it < 8; it++) {
            int idx = tid + 256 * it;              // 2048 chunks
            int r = idx >> 4, ch = idx & 15;
            const __nv_bfloat16* src = hsrc + (size_t)r * HID + q * 128 + ch * 8;
            uint32_t dst = (uint32_t)__cvta_generic_to_shared(
                sm + OFF_A + (r * ST + q * 128 + ch * 8) * 2);
            asm volatile("cp.async.cg.shared.global [%0], [%1], 16;" :: "r"(dst), "l"(src));
        }
        asm volatile("cp.async.commit_group;" ::: "memory");
    };

    auto mma_q = [&](int q) {
#pragma unroll
        for (int kkl = 0; kkl < 8; kkl++) {
            const int kg = (q * 8 + kkl) * 32;
            uint32_t a0[4], a1[4], b01[4], b23[4];
            ldsm_x4(a0, aaddr[0] + kg);
            ldsm_x4(a1, aaddr[1] + kg);
            ldsm_x4(b01, baddr[0] + kg);
            ldsm_x4(b23, baddr[1] + kg);
            mma_bf16(acc[0][0], a0, b01);     mma_bf16(acc[0][1], a0, b01 + 2);
            mma_bf16(acc[0][2], a0, b23);     mma_bf16(acc[0][3], a0, b23 + 2);
            mma_bf16(acc[1][0], a1, b01);     mma_bf16(acc[1][1], a1, b01 + 2);
            mma_bf16(acc[1][2], a1, b23);     mma_bf16(acc[1][3], a1, b23 + 2);
        }
    };

#pragma unroll 1
    for (int t = 0; t < TSTEPS; t++) {
        // ---- xg prefetch (independent of flags) ----
        uint32_t xr[2][4][2];
        {
            const size_t rb = (size_t)t * BPAD + m0 + mw * 32 + gr;
#pragma unroll
            for (int mf = 0; mf < 2; mf++)
#pragma unroll
                for (int nf = 0; nf < 4; nf++) {
                    const size_t r0 = (rb + mf * 16) * 1024 + colu + nf * 4;
                    xr[mf][nf][0] = __ldg(xg32 + r0);
                    xr[mf][nf][1] = __ldg(xg32 + r0 + 8 * 1024);
                }
        }

#pragma unroll
        for (int mf = 0; mf < 2; mf++)
#pragma unroll
            for (int nf = 0; nf < 4; nf++)
#pragma unroll
                for (int r = 0; r < 4; r++) acc[mf][nf][r] = 0.f;

        if (t > 0) {
            // ---- lane-per-slot acquire spin: all 32 writers finished t-1 ----
            const unsigned target = (unsigned)t;
            unsigned v;
            do {
                asm volatile("ld.acquire.gpu.global.u32 %0, [%1];"
                             : "=r"(v) : "l"(poll_flag) : "memory");
            } while (__any_sync(0xffffffffu, v < target));

            const __nv_bfloat16* hsrc = g_hb + ((size_t)(t - 1) * BPAD + m0) * HID;
            load_q(hsrc, 0); load_q(hsrc, 1); load_q(hsrc, 2); load_q(hsrc, 3);

            asm volatile("cp.async.wait_group 3;" ::: "memory");
            __syncthreads();
            mma_q(0);
            asm volatile("cp.async.wait_group 2;" ::: "memory");
            __syncthreads();
            mma_q(1);
            asm volatile("cp.async.wait_group 1;" ::: "memory");
            __syncthreads();
            mma_q(2);
            asm volatile("cp.async.wait_group 0;" ::: "memory");
            __syncthreads();
            mma_q(3);
        }

        // ---- epilogue: + xg, + bias, gate exchange, cell update -> Hsb ----
#pragma unroll
        for (int mf = 0; mf < 2; mf++) {
            const int row = mw * 32 + mf * 16 + gr;
#pragma unroll
            for (int nf = 0; nf < 4; nf++) {
                float2 x0 = __bfloat1622float2(*(__nv_bfloat162*)&xr[mf][nf][0]);
                float2 x1 = __bfloat1622float2(*(__nv_bfloat162*)&xr[mf][nf][1]);
                float b0 = even ? pb4[nf].x : pb4[nf].z;
                float b1 = even ? pb4[nf].y : pb4[nf].w;
                float v0 = acc[mf][nf][0] + x0.x + b0;
                float v1 = acc[mf][nf][1] + x0.y + b1;
                float v2 = acc[mf][nf][2] + x1.x + b0;
                float v3 = acc[mf][nf][3] + x1.y + b1;
                float s0 = __shfl_xor_sync(0xffffffffu, v0, 1);
                float s1 = __shfl_xor_sync(0xffffffffu, v1, 1);
                float s2 = __shfl_xor_sync(0xffffffffu, v2, 1);
                float s3 = __shfl_xor_sync(0xffffffffu, v3, 1);
                if (even) {
                    const int jc = nw * 8 + 2 * nf + (tg >> 1);
                    float ig0 = fast_sigmoid(v0), fg0 = fast_sigmoid(v1);
                    float gt0 = fast_tanh(s0),    ot0 = fast_sigmoid(s1);
                    float c0 = fg0 * creg[mf][nf][0] + ig0 * gt0;
                    creg[mf][nf][0] = c0;
                    Hsb[row * HS2 + jc] = __float2bfloat16_rn(ot0 * fast_tanh(c0));
                    float ig1 = fast_sigmoid(v2), fg1 = fast_sigmoid(v3);
                    float gt1 = fast_tanh(s2),    ot1 = fast_sigmoid(s3);
                    float c1 = fg1 * creg[mf][nf][1] + ig1 * gt1;
                    creg[mf][nf][1] = c1;
                    Hsb[(row + 8) * HS2 + jc] = __float2bfloat16_rn(ot1 * fast_tanh(c1));
                }
            }
        }
        __syncthreads();

        // ---- coalesced flush: 256 x 16B stores ----
        {
            const int row = tid >> 1, half = tid & 1;
            uint4 v = *(uint4*)&Hsb[row * HS2 + half * 8];
            *(uint4*)(g_hb + (size_t)t * BPAD * HID +
                      (size_t)(m0 + row) * HID + blockIdx.y * 16 + half * 8) = v;
        }
        __syncthreads();
        if (tid == 0) {
            asm volatile("st.release.gpu.global.u32 [%0], %1;"
                         :: "l"(my_flag), "r"((unsigned)(t + 1)) : "memory");
        }
    }
}

// -------------------------------------------------------------------------
// FC (bf16 mma): out[b][t][o] = sigmoid(g_hb[t][b] . W_fc[o] + b_fc[o])
// -------------------------------------------------------------------------
#define XA_STRIDE 40
__global__ __launch_bounds__(256) void fc_gemm_kernel(
    const float* __restrict__ bfc,
    float* __restrict__ out)
{
    __shared__ __nv_bfloat16 As[2][128 * XA_STRIDE];
    __shared__ __nv_bfloat16 Bs[2][128 * XA_STRIDE];
    const int tid = threadIdx.x;
    const int lid = tid & 31, wid = tid >> 5;
    const int tg = lid & 3, gr = lid >> 2;
    const int mw = wid & 3, nw = wid >> 2;
    const size_t R0 = (size_t)blockIdx.x * 128;

    float acc[2][8][4];
#pragma unroll
    for (int mf = 0; mf < 2; mf++)
#pragma unroll
        for (int nf = 0; nf < 8; nf++)
#pragma unroll
            for (int r = 0; r < 4; r++) acc[mf][nf][r] = 0.f;

    auto load_stage = [&](int s) {
        const int buf = s & 1;
        const int k0 = s * 32;
#pragma unroll
        for (int it = 0; it < 2; it++) {
            int idx = tid + 256 * it;
            int r = idx >> 2, ch = idx & 3;
            const __nv_bfloat16* src = g_hb + (R0 + r) * HID + k0 + ch * 8;
            uint32_t dst = (uint32_t)__cvta_generic_to_shared(&As[buf][r * XA_STRIDE + ch * 8]);
            asm volatile("cp.async.cg.shared.global [%0], [%1], 16;" :: "r"(dst), "l"(src));
        }
#pragma unroll
        for (int it = 0; it < 2; it++) {
            int idx = tid + 256 * it;
            int r = idx >> 2, ch = idx & 3;
            const __nv_bfloat16* src = g_Wf + (size_t)r * 512 + k0 + ch * 8;
            uint32_t dst = (uint32_t)__cvta_generic_to_shared(&Bs[buf][r * XA_STRIDE + ch * 8]);
            asm volatile("cp.async.cg.shared.global [%0], [%1], 16;" :: "r"(dst), "l"(src));
        }
        asm volatile("cp.async.commit_group;" ::: "memory");
    };

    load_stage(0);
#pragma unroll 1
    for (int s = 0; s < 16; s++) {
        if (s + 1 < 16) {
            load_stage(s + 1);
            asm volatile("cp.async.wait_group 1;" ::: "memory");
        } else {
            asm volatile("cp.async.wait_group 0;" ::: "memory");
        }
        __syncthreads();
        const int buf = s & 1;
        const __nv_bfloat16* Ab = &As[buf][(mw * 32) * XA_STRIDE];
        const __nv_bfloat16* Bb = &Bs[buf][(nw * 64) * XA_STRIDE];
#pragma unroll
        for (int ks = 0; ks < 2; ks++) {
            const int k = ks * 16 + tg * 2;
            uint32_t a[2][4];
#pragma unroll
            for (int mf = 0; mf < 2; mf++) {
                const __nv_bfloat16* p = Ab + (mf * 16 + gr) * XA_STRIDE + k;
                a[mf][0] = *(const uint32_t*)p;
                a[mf][1] = *(const uint32_t*)(p + 8 * XA_STRIDE);
                a[mf][2] = *(const uint32_t*)(p + 8);
                a[mf][3] = *(const uint32_t*)(p + 8 * XA_STRIDE + 8);
            }
#pragma unroll
            for (int nf = 0; nf < 8; nf++) {
                const __nv_bfloat16* p = Bb + (nf * 8 + gr) * XA_STRIDE + k;
                uint32_t b[2];
                b[0] = *(const uint32_t*)p;
                b[1] = *(const uint32_t*)(p + 8);
#pragma unroll
                for (int mf = 0; mf < 2; mf++) mma_bf16(acc[mf][nf], a[mf], b);
            }
        }
        __syncthreads();
    }

#pragma unroll
    for (int mf = 0; mf < 2; mf++)
#pragma unroll
        for (int nf = 0; nf < 8; nf++) {
            const int c = nw * 64 + nf * 8 + 2 * tg;
            if (c >= NOUT) continue;
#pragma unroll
            for (int half = 0; half < 2; half++) {
                size_t R = R0 + mw * 32 + mf * 16 + gr + half * 8;
                int t = (int)(R >> 9);
                int b = (int)(R & 511);
                if (b < BATCH) {
                    float* dst = out + ((size_t)b * TSTEPS + t) * NOUT + c;
                    dst[0] = fast_sigmoid(acc[mf][nf][half * 2 + 0] + bfc[c]);
                    dst[1] = fast_sigmoid(acc[mf][nf][half * 2 + 1] + bfc[c + 1]);
                }
            }
        }
}

// -------------------------------------------------------------------------
extern "C" void kernel_launch(void* const* d_in, const int* in_sizes, int n_in,
                              void* d_out, int out_size) {
    const float* inp  = (const float*)d_in[0];
    const float* Wih  = (const float*)d_in[1];
    const float* Whh  = (const float*)d_in[2];
    const float* bih  = (const float*)d_in[3];
    const float* bhh  = (const float*)d_in[4];
    const float* Wfc  = (const float*)d_in[5];
    const float* bfc  = (const float*)d_in[6];
    float* out = (float*)d_out;

    cudaFuncSetAttribute(lstm_persist_kernel,
                         cudaFuncAttributeMaxDynamicSharedMemorySize, PERSIST_SMEM);
    cudaFuncSetAttribute(xg_gemm_kernel,
                         cudaFuncAttributeMaxDynamicSharedMemorySize, XG_SMEM);

    zero_state_kernel<<<16, 256>>>();
    {
        long long total = (long long)TSTEPS * BATCH * EMB;
        int blocks = (int)((total + 255) / 256);
        prep_xbf_kernel<<<blocks, 256>>>(inp);
    }
    zero_xbf_pad_kernel<<<(TSTEPS * 12 * EMB / 2 + 255) / 256, 256>>>();
    prep_w_kernel<<<(2048 * 1024) / 256, 256>>>(Wih, Whh, bih, bhh, Wfc);

    xg_gemm_kernel<<<dim3(16, MROWS / 128), 256, XG_SMEM>>>();

    lstm_persist_kernel<<<dim3(4, 32), 256, PERSIST_SMEM>>>();

    fc_gemm_kernel<<<1024, 256>>>(bfc, out);
}

// round 14
// speedup vs baseline: 1.2119x; 1.2119x over previous
#include <cuda_runtime.h>
#include <cuda_bf16.h>
#include <math.h>
#include <stdint.h>

#define BATCH 500
#define BPAD 512
#define TSTEPS 256
#define EMB 512
#define HID 512
#define NOUT 100
#define TBSTRIDE (TSTEPS * EMB)
#define MROWS (TSTEPS * BPAD)

// ------------------------- device globals (scratch) -------------------------
__device__ __nv_bfloat16 g_xbf[(size_t)MROWS * EMB];        // 134MB  [t*512+b][e]
__device__ __nv_bfloat16 g_Wx[2048 * 512];
__device__ __nv_bfloat16 g_Wh[2048 * 512];
__device__ __nv_bfloat16 g_Wf[128 * 512];
__device__ float g_pb[2048];
__device__ __nv_bfloat16 g_xg[(size_t)MROWS * 2048];        // 540MB xg bf16
__device__ __nv_bfloat16 g_hb[(size_t)TSTEPS * BPAD * HID]; // 134MB bf16 h, t-indexed
__device__ unsigned g_bar[8 * 32];                          // counter per m-group, 128B apart

__device__ __forceinline__ float fast_sigmoid(float x) {
    return 1.f / (1.f + __expf(-x));
}
__device__ __forceinline__ float fast_tanh(float x) {
    float ax = fabsf(x);
    float e = __expf(-2.f * ax);
    float r = (1.f - e) / (1.f + e);
    return copysignf(r, x);
}

// ------------------------- init / prep -------------------------
__global__ void zero_state_kernel() {
    int idx = blockIdx.x * blockDim.x + threadIdx.x;
    if (idx < 8 * 32) g_bar[idx] = 0u;
}

__global__ void prep_xbf_kernel(const float* __restrict__ inp) {
    long long idx = (long long)blockIdx.x * blockDim.x + threadIdx.x;
    if (idx >= (long long)TSTEPS * BATCH * EMB) return;
    int e = (int)(idx & 511);
    long long r = idx >> 9;
    int b = (int)(r % BATCH);
    int t = (int)(r / BATCH);
    float v = inp[(size_t)b * TBSTRIDE + (size_t)t * EMB + e];
    g_xbf[((size_t)t * BPAD + b) * EMB + e] = __float2bfloat16_rn(v);
}

__global__ void zero_xbf_pad_kernel() {
    int idx = blockIdx.x * blockDim.x + threadIdx.x;
    int total = TSTEPS * 12 * EMB / 2;
    if (idx >= total) return;
    int per_t = 12 * EMB / 2;
    int t = idx / per_t;
    int o = idx - t * per_t;
    ((uint32_t*)(g_xbf + ((size_t)t * BPAD + BATCH) * EMB))[o] = 0u;
}

__global__ void prep_w_kernel(const float* __restrict__ Wih,
                              const float* __restrict__ Whh,
                              const float* __restrict__ bih,
                              const float* __restrict__ bhh,
                              const float* __restrict__ Wfc) {
    int idx = blockIdx.x * blockDim.x + threadIdx.x;
    int np = idx >> 10;
    int k  = idx & 1023;
    int j = np >> 2, gate = np & 3;
    int n = gate * HID + j;
    if (k < 512) g_Wx[np * 512 + k] = __float2bfloat16_rn(Wih[(size_t)n * EMB + k]);
    else         g_Wh[np * 512 + (k - 512)] = __float2bfloat16_rn(Whh[(size_t)n * HID + (k - 512)]);
    if (idx < 2048) {
        int jj = idx >> 2, gg = idx & 3;
        g_pb[idx] = bih[gg * HID + jj] + bhh[gg * HID + jj];
    }
    if (idx < 128 * 512) {
        int fn = idx >> 9, fk = idx & 511;
        g_Wf[idx] = (fn < NOUT) ? __float2bfloat16_rn(Wfc[(size_t)fn * 512 + fk])
                                : __float2bfloat16_rn(0.f);
    }
}

// ------------------------- mma / ldmatrix helpers -------------------------
__device__ __forceinline__ void mma_bf16(float* d, const uint32_t* a, const uint32_t* b) {
    asm volatile(
        "mma.sync.aligned.m16n8k16.row.col.f32.bf16.bf16.f32 "
        "{%0,%1,%2,%3}, {%4,%5,%6,%7}, {%8,%9}, {%0,%1,%2,%3};"
        : "+f"(d[0]), "+f"(d[1]), "+f"(d[2]), "+f"(d[3])
        : "r"(a[0]), "r"(a[1]), "r"(a[2]), "r"(a[3]), "r"(b[0]), "r"(b[1]));
}
__device__ __forceinline__ void ldsm_x4(uint32_t* r, uint32_t addr) {
    asm volatile("ldmatrix.sync.aligned.m8n8.x4.shared.b16 {%0,%1,%2,%3}, [%4];"
                 : "=r"(r[0]), "=r"(r[1]), "=r"(r[2]), "=r"(r[3]) : "r"(addr));
}

// -------------------------------------------------------------------------
// Big parallel GEMM: g_xg[131072][2048](bf16) = g_xbf @ g_Wx^T  (unchanged)
// -------------------------------------------------------------------------
#define XS2 72
#define XBUF (128 * XS2)
#define XG_SMEM (4 * XBUF * 2)       // 73728

__global__ __launch_bounds__(256) void xg_gemm_kernel() {
    extern __shared__ __nv_bfloat16 xsm[];
    __nv_bfloat16* As = xsm;
    __nv_bfloat16* Bs = xsm + 2 * XBUF;
    const int tid = threadIdx.x;
    const int lid = tid & 31, wid = tid >> 5;
    const int tg = lid & 3, gr = lid >> 2;
    const int mw = wid & 3, nw = wid >> 2;
    const size_t R0 = (size_t)blockIdx.y * 128;
    const int n0 = blockIdx.x * 128;

    float acc[2][8][4];
#pragma unroll
    for (int mf = 0; mf < 2; mf++)
#pragma unroll
        for (int nf = 0; nf < 8; nf++)
#pragma unroll
            for (int r = 0; r < 4; r++) acc[mf][nf][r] = 0.f;

    uint32_t aA[2][2], bB[2][4];
    {
        const uint32_t abase = (uint32_t)__cvta_generic_to_shared(As);
        const uint32_t bbase = (uint32_t)__cvta_generic_to_shared(Bs);
        const int arow = mw * 32 + (lid & 15);
        const int acol = (lid >> 4) << 3;
        const int brb = nw * 64 + ((lid >> 4) << 3) + (lid & 7);
        const int bcol = ((lid >> 3) & 1) << 3;
#pragma unroll
        for (int buf = 0; buf < 2; buf++) {
#pragma unroll
            for (int mf = 0; mf < 2; mf++)
                aA[buf][mf] = abase + (uint32_t)(buf * XBUF + (arow + mf * 16) * XS2 + acol) * 2;
#pragma unroll
            for (int p = 0; p < 4; p++)
                bB[buf][p] = bbase + (uint32_t)(buf * XBUF + (brb + p * 16) * XS2 + bcol) * 2;
        }
    }

    auto load_stage = [&](int s) {
        const int buf = s & 1;
        const int k0 = s * 64;
#pragma unroll
        for (int it = 0; it < 4; it++) {
            int idx = tid + 256 * it;
            int r = idx >> 3, ch = idx & 7;
            const __nv_bfloat16* src = g_xbf + (R0 + r) * EMB + k0 + ch * 8;
            uint32_t dst = (uint32_t)__cvta_generic_to_shared(&As[buf * XBUF + r * XS2 + ch * 8]);
            asm volatile("cp.async.cg.shared.global [%0], [%1], 16;" :: "r"(dst), "l"(src));
        }
#pragma unroll
        for (int it = 0; it < 4; it++) {
            int idx = tid + 256 * it;
            int r = idx >> 3, ch = idx & 7;
            const __nv_bfloat16* src = g_Wx + (size_t)(n0 + r) * 512 + k0 + ch * 8;
            uint32_t dst = (uint32_t)__cvta_generic_to_shared(&Bs[buf * XBUF + r * XS2 + ch * 8]);
            asm volatile("cp.async.cg.shared.global [%0], [%1], 16;" :: "r"(dst), "l"(src));
        }
        asm volatile("cp.async.commit_group;" ::: "memory");
    };

    load_stage(0);
#pragma unroll 1
    for (int s = 0; s < 8; s++) {
        if (s + 1 < 8) {
            load_stage(s + 1);
            asm volatile("cp.async.wait_group 1;" ::: "memory");
        } else {
            asm volatile("cp.async.wait_group 0;" ::: "memory");
        }
        __syncthreads();
        const int buf = s & 1;
#pragma unroll
        for (int kk = 0; kk < 4; kk++) {
            uint32_t a0[4], a1[4];
            ldsm_x4(a0, aA[buf][0] + kk * 32);
            ldsm_x4(a1, aA[buf][1] + kk * 32);
#pragma unroll
            for (int p = 0; p < 4; p++) {
                uint32_t bb[4];
                ldsm_x4(bb, bB[buf][p] + kk * 32);
                mma_bf16(acc[0][2 * p],     a0, bb);
                mma_bf16(acc[0][2 * p + 1], a0, bb + 2);
                mma_bf16(acc[1][2 * p],     a1, bb);
                mma_bf16(acc[1][2 * p + 1], a1, bb + 2);
            }
        }
        __syncthreads();
    }

    uint32_t* xg32 = (uint32_t*)g_xg;
#pragma unroll
    for (int mf = 0; mf < 2; mf++)
#pragma unroll
        for (int nf = 0; nf < 8; nf++) {
            size_t R = R0 + mw * 32 + mf * 16 + gr;
            int c = n0 + nw * 64 + nf * 8 + 2 * tg;
            __nv_bfloat162 lo = __float22bfloat162_rn(make_float2(acc[mf][nf][0], acc[mf][nf][1]));
            __nv_bfloat162 hi = __float22bfloat162_rn(make_float2(acc[mf][nf][2], acc[mf][nf][3]));
            xg32[R * 1024 + (c >> 1)]       = *(uint32_t*)&lo;
            xg32[(R + 8) * 1024 + (c >> 1)] = *(uint32_t*)&hi;
        }
}

// -------------------------------------------------------------------------
// Persistent LSTM: 256 CTAs (8 m-groups of 64 rows x 32 n-tiles), 2 CTAs/SM.
// Per CTA: M=64, N=64, K=512. A streamed as 4 quarters (64x128) in 2 buffers.
// -------------------------------------------------------------------------
#define ST 520
#define AST 136
#define ABUF (64 * AST * 2)                     // 17408 bytes
#define HS2 24
#define OFF_WH 0
#define OFF_A  (64 * ST * 2)                    // 66560
#define OFF_HS (OFF_A + 2 * ABUF)               // 101376
#define PERSIST_SMEM (OFF_HS + 64 * HS2 * 2)    // 104448

__global__ __launch_bounds__(256, 2) void lstm_persist_kernel() {
    extern __shared__ char sm[];
    __nv_bfloat16* Hsb = (__nv_bfloat16*)(sm + OFF_HS);

    const int tid = threadIdx.x;
    const int lid = tid & 31, wid = tid >> 5;
    const int tg = lid & 3, gr = lid >> 2;
    const int mw = wid & 1, nw = wid >> 1;      // 2 m-warps x 4 n-warps
    const int mblk = blockIdx.x;                // 8 m-groups
    const int m0 = mblk * 64;
    const int n0 = blockIdx.y * 64;
    const bool even = (tg & 1) == 0;

    unsigned* bar = &g_bar[mblk * 32];

    // ---- Wh slice (64 rows x 512 bf16) resident ----
#pragma unroll
    for (int it = 0; it < 16; it++) {
        int idx = tid + 256 * it;
        int r = idx >> 6, ch = idx & 63;
        const __nv_bfloat16* src = g_Wh + (size_t)(n0 + r) * 512 + ch * 8;
        uint32_t dst = (uint32_t)__cvta_generic_to_shared(sm + OFF_WH + (r * ST + ch * 8) * 2);
        asm volatile("cp.async.cg.shared.global [%0], [%1], 16;" :: "r"(dst), "l"(src));
    }
    asm volatile("cp.async.commit_group;" ::: "memory");
    asm volatile("cp.async.wait_group 0;" ::: "memory");
    __syncthreads();

    // ldmatrix addresses: A per (buf, mf); B one x4 per warp (16 rows)
    uint32_t aaddr[2][2], baddr;
    {
        const uint32_t smbase = (uint32_t)__cvta_generic_to_shared(sm);
        const int arow = mw * 32 + (lid & 15);
        const int acol = (lid >> 4) << 3;
#pragma unroll
        for (int buf = 0; buf < 2; buf++)
#pragma unroll
            for (int mf = 0; mf < 2; mf++)
                aaddr[buf][mf] = smbase + OFF_A + buf * ABUF
                               + (uint32_t)((arow + mf * 16) * AST + acol) * 2;
        const int brow = nw * 16 + ((lid >> 4) << 3) + (lid & 7);
        const int bcol = ((lid >> 3) & 1) << 3;
        baddr = smbase + OFF_WH + (uint32_t)(brow * ST + bcol) * 2;
    }

    float4 pb4[2];
#pragma unroll
    for (int nf = 0; nf < 2; nf++) {
        int jc = nw * 4 + 2 * nf + (tg >> 1);
        pb4[nf] = *(const float4*)&g_pb[n0 + jc * 4];
    }

    float creg[2][2][2];
#pragma unroll
    for (int mf = 0; mf < 2; mf++)
#pragma unroll
        for (int nf = 0; nf < 2; nf++) { creg[mf][nf][0] = 0.f; creg[mf][nf][1] = 0.f; }

    const uint32_t* xg32 = (const uint32_t*)g_xg;
    const int colu = (n0 + nw * 16 + 2 * tg) >> 1;

    float acc[2][2][4];

    // quarter loader: 64 rows x 128 bf16 = 1024 x 16B chunks
    auto load_q = [&](const __nv_bfloat16* hsrc, int q, int buf) {
#pragma unroll
        for (int it = 0; it < 4; it++) {
            int idx = tid + 256 * it;
            int r = idx >> 4, ch = idx & 15;
            const __nv_bfloat16* src = hsrc + (size_t)r * HID + q * 128 + ch * 8;
            uint32_t dst = (uint32_t)__cvta_generic_to_shared(
                sm + OFF_A + buf * ABUF + (r * AST + ch * 8) * 2);
            asm volatile("cp.async.cg.shared.global [%0], [%1], 16;" :: "r"(dst), "l"(src));
        }
        asm volatile("cp.async.commit_group;" ::: "memory");
    };

    auto mma_q = [&](int q, int buf) {
#pragma unroll
        for (int kkl = 0; kkl < 8; kkl++) {
            uint32_t a0[4], a1[4], bb[4];
            ldsm_x4(a0, aaddr[buf][0] + kkl * 32);
            ldsm_x4(a1, aaddr[buf][1] + kkl * 32);
            ldsm_x4(bb, baddr + (q * 8 + kkl) * 32);
            mma_bf16(acc[0][0], a0, bb);     mma_bf16(acc[0][1], a0, bb + 2);
            mma_bf16(acc[1][0], a1, bb);     mma_bf16(acc[1][1], a1, bb + 2);
        }
    };

#pragma unroll 1
    for (int t = 0; t < TSTEPS; t++) {
        // ---- xg prefetch (independent of barrier) ----
        uint32_t xr[2][2][2];
        {
            const size_t rb = (size_t)t * BPAD + m0 + mw * 32 + gr;
#pragma unroll
            for (int mf = 0; mf < 2; mf++)
#pragma unroll
                for (int nf = 0; nf < 2; nf++) {
                    const size_t r0 = (rb + mf * 16) * 1024 + colu + nf * 4;
                    xr[mf][nf][0] = __ldg(xg32 + r0);
                    xr[mf][nf][1] = __ldg(xg32 + r0 + 8 * 1024);
                }
        }

#pragma unroll
        for (int mf = 0; mf < 2; mf++)
#pragma unroll
            for (int nf = 0; nf < 2; nf++)
#pragma unroll
                for (int r = 0; r < 4; r++) acc[mf][nf][r] = 0.f;

        if (t > 0) {
            // ---- spin on the m-group counter (all threads, one address) ----
            const unsigned target = 32u * (unsigned)t;
            unsigned v;
            do {
                asm volatile("ld.acquire.gpu.global.u32 %0, [%1];"
                             : "=r"(v) : "l"(bar) : "memory");
            } while (v < target);

            const __nv_bfloat16* hsrc = g_hb + ((size_t)(t - 1) * BPAD + m0) * HID;
            load_q(hsrc, 0, 0);
            load_q(hsrc, 1, 1);
            asm volatile("cp.async.wait_group 1;" ::: "memory");
            __syncthreads();
            mma_q(0, 0);
            __syncthreads();
            load_q(hsrc, 2, 0);
            asm volatile("cp.async.wait_group 1;" ::: "memory");
            __syncthreads();
            mma_q(1, 1);
            __syncthreads();
            load_q(hsrc, 3, 1);
            asm volatile("cp.async.wait_group 1;" ::: "memory");
            __syncthreads();
            mma_q(2, 0);
            asm volatile("cp.async.wait_group 0;" ::: "memory");
            __syncthreads();
            mma_q(3, 1);
        }

        // ---- epilogue: + xg, + bias, gate exchange, cell update -> Hsb ----
#pragma unroll
        for (int mf = 0; mf < 2; mf++) {
            const int row = mw * 32 + mf * 16 + gr;
#pragma unroll
            for (int nf = 0; nf < 2; nf++) {
                float2 x0 = __bfloat1622float2(*(__nv_bfloat162*)&xr[mf][nf][0]);
                float2 x1 = __bfloat1622float2(*(__nv_bfloat162*)&xr[mf][nf][1]);
                float b0 = even ? pb4[nf].x : pb4[nf].z;
                float b1 = even ? pb4[nf].y : pb4[nf].w;
                float v0 = acc[mf][nf][0] + x0.x + b0;
                float v1 = acc[mf][nf][1] + x0.y + b1;
                float v2 = acc[mf][nf][2] + x1.x + b0;
                float v3 = acc[mf][nf][3] + x1.y + b1;
                float s0 = __shfl_xor_sync(0xffffffffu, v0, 1);
                float s1 = __shfl_xor_sync(0xffffffffu, v1, 1);
                float s2 = __shfl_xor_sync(0xffffffffu, v2, 1);
                float s3 = __shfl_xor_sync(0xffffffffu, v3, 1);
                if (even) {
                    const int jc = nw * 4 + 2 * nf + (tg >> 1);
                    float ig0 = fast_sigmoid(v0), fg0 = fast_sigmoid(v1);
                    float gt0 = fast_tanh(s0),    ot0 = fast_sigmoid(s1);
                    float c0 = fg0 * creg[mf][nf][0] + ig0 * gt0;
                    creg[mf][nf][0] = c0;
                    Hsb[row * HS2 + jc] = __float2bfloat16_rn(ot0 * fast_tanh(c0));
                    float ig1 = fast_sigmoid(v2), fg1 = fast_sigmoid(v3);
                    float gt1 = fast_tanh(s2),    ot1 = fast_sigmoid(s3);
                    float c1 = fg1 * creg[mf][nf][1] + ig1 * gt1;
                    creg[mf][nf][1] = c1;
                    Hsb[(row + 8) * HS2 + jc] = __float2bfloat16_rn(ot1 * fast_tanh(c1));
                }
            }
        }
        __syncthreads();

        // ---- coalesced flush: 128 x 16B stores (64 rows x 16 cols) ----
        if (tid < 128) {
            const int row = tid >> 1, half = tid & 1;
            uint4 v = *(uint4*)&Hsb[row * HS2 + half * 8];
            *(uint4*)(g_hb + (size_t)t * BPAD * HID +
                      (size_t)(m0 + row) * HID + blockIdx.y * 16 + half * 8) = v;
        }
        __syncthreads();
        if (tid == 0) {
            asm volatile("red.release.gpu.global.add.u32 [%0], 1;"
                         :: "l"(bar) : "memory");
        }
    }
}

// -------------------------------------------------------------------------
// FC (bf16 mma): out[b][t][o] = sigmoid(g_hb[t][b] . W_fc[o] + b_fc[o])
// -------------------------------------------------------------------------
#define XA_STRIDE 40
__global__ __launch_bounds__(256) void fc_gemm_kernel(
    const float* __restrict__ bfc,
    float* __restrict__ out)
{
    __shared__ __nv_bfloat16 As[2][128 * XA_STRIDE];
    __shared__ __nv_bfloat16 Bs[2][128 * XA_STRIDE];
    const int tid = threadIdx.x;
    const int lid = tid & 31, wid = tid >> 5;
    const int tg = lid & 3, gr = lid >> 2;
    const int mw = wid & 3, nw = wid >> 2;
    const size_t R0 = (size_t)blockIdx.x * 128;

    float acc[2][8][4];
#pragma unroll
    for (int mf = 0; mf < 2; mf++)
#pragma unroll
        for (int nf = 0; nf < 8; nf++)
#pragma unroll
            for (int r = 0; r < 4; r++) acc[mf][nf][r] = 0.f;

    auto load_stage = [&](int s) {
        const int buf = s & 1;
        const int k0 = s * 32;
#pragma unroll
        for (int it = 0; it < 2; it++) {
            int idx = tid + 256 * it;
            int r = idx >> 2, ch = idx & 3;
            const __nv_bfloat16* src = g_hb + (R0 + r) * HID + k0 + ch * 8;
            uint32_t dst = (uint32_t)__cvta_generic_to_shared(&As[buf][r * XA_STRIDE + ch * 8]);
            asm volatile("cp.async.cg.shared.global [%0], [%1], 16;" :: "r"(dst), "l"(src));
        }
#pragma unroll
        for (int it = 0; it < 2; it++) {
            int idx = tid + 256 * it;
            int r = idx >> 2, ch = idx & 3;
            const __nv_bfloat16* src = g_Wf + (size_t)r * 512 + k0 + ch * 8;
            uint32_t dst = (uint32_t)__cvta_generic_to_shared(&Bs[buf][r * XA_STRIDE + ch * 8]);
            asm volatile("cp.async.cg.shared.global [%0], [%1], 16;" :: "r"(dst), "l"(src));
        }
        asm volatile("cp.async.commit_group;" ::: "memory");
    };

    load_stage(0);
#pragma unroll 1
    for (int s = 0; s < 16; s++) {
        if (s + 1 < 16) {
            load_stage(s + 1);
            asm volatile("cp.async.wait_group 1;" ::: "memory");
        } else {
            asm volatile("cp.async.wait_group 0;" ::: "memory");
        }
        __syncthreads();
        const int buf = s & 1;
        const __nv_bfloat16* Ab = &As[buf][(mw * 32) * XA_STRIDE];
        const __nv_bfloat16* Bb = &Bs[buf][(nw * 64) * XA_STRIDE];
#pragma unroll
        for (int ks = 0; ks < 2; ks++) {
            const int k = ks * 16 + tg * 2;
            uint32_t a[2][4];
#pragma unroll
            for (int mf = 0; mf < 2; mf++) {
                const __nv_bfloat16* p = Ab + (mf * 16 + gr) * XA_STRIDE + k;
                a[mf][0] = *(const uint32_t*)p;
                a[mf][1] = *(const uint32_t*)(p + 8 * XA_STRIDE);
                a[mf][2] = *(const uint32_t*)(p + 8);
                a[mf][3] = *(const uint32_t*)(p + 8 * XA_STRIDE + 8);
            }
#pragma unroll
            for (int nf = 0; nf < 8; nf++) {
                const __nv_bfloat16* p = Bb + (nf * 8 + gr) * XA_STRIDE + k;
                uint32_t b[2];
                b[0] = *(const uint32_t*)p;
                b[1] = *(const uint32_t*)(p + 8);
#pragma unroll
                for (int mf = 0; mf < 2; mf++) mma_bf16(acc[mf][nf], a[mf], b);
            }
        }
        __syncthreads();
    }

#pragma unroll
    for (int mf = 0; mf < 2; mf++)
#pragma unroll
        for (int nf = 0; nf < 8; nf++) {
            const int c = nw * 64 + nf * 8 + 2 * tg;
            if (c >= NOUT) continue;
#pragma unroll
            for (int half = 0; half < 2; half++) {
                size_t R = R0 + mw * 32 + mf * 16 + gr + half * 8;
                int t = (int)(R >> 9);
                int b = (int)(R & 511);
                if (b < BATCH) {
                    float* dst = out + ((size_t)b * TSTEPS + t) * NOUT + c;
                    dst[0] = fast_sigmoid(acc[mf][nf][half * 2 + 0] + bfc[c]);
                    dst[1] = fast_sigmoid(acc[mf][nf][half * 2 + 1] + bfc[c + 1]);
                }
            }
        }
}

// -------------------------------------------------------------------------
extern "C" void kernel_launch(void* const* d_in, const int* in_sizes, int n_in,
                              void* d_out, int out_size) {
    const float* inp  = (const float*)d_in[0];
    const float* Wih  = (const float*)d_in[1];
    const float* Whh  = (const float*)d_in[2];
    const float* bih  = (const float*)d_in[3];
    const float* bhh  = (const float*)d_in[4];
    const float* Wfc  = (const float*)d_in[5];
    const float* bfc  = (const float*)d_in[6];
    float* out = (float*)d_out;

    cudaFuncSetAttribute(lstm_persist_kernel,
                         cudaFuncAttributeMaxDynamicSharedMemorySize, PERSIST_SMEM);
    cudaFuncSetAttribute(xg_gemm_kernel,
                         cudaFuncAttributeMaxDynamicSharedMemorySize, XG_SMEM);

    zero_state_kernel<<<1, 256>>>();
    {
        long long total = (long long)TSTEPS * BATCH * EMB;
        int blocks = (int)((total + 255) / 256);
        prep_xbf_kernel<<<blocks, 256>>>(inp);
    }
    zero_xbf_pad_kernel<<<(TSTEPS * 12 * EMB / 2 + 255) / 256, 256>>>();
    prep_w_kernel<<<(2048 * 1024) / 256, 256>>>(Wih, Whh, bih, bhh, Wfc);

    xg_gemm_kernel<<<dim3(16, MROWS / 128), 256, XG_SMEM>>>();

    lstm_persist_kernel<<<dim3(8, 32), 256, PERSIST_SMEM>>>();

    fc_gemm_kernel<<<1024, 256>>>(bfc, out);
}

// round 15
// speedup vs baseline: 1.2482x; 1.0300x over previous
#include <cuda_runtime.h>
#include <cuda_bf16.h>
#include <math.h>
#include <stdint.h>

#define BATCH 500
#define BPAD 512
#define TSTEPS 256
#define EMB 512
#define HID 512
#define NOUT 100
#define TBSTRIDE (TSTEPS * EMB)
#define MROWS (TSTEPS * BPAD)

// ------------------------- device globals (scratch) -------------------------
__device__ __nv_bfloat16 g_xbf[(size_t)MROWS * EMB];        // 134MB  [t*512+b][e]
__device__ __nv_bfloat16 g_Wx[2048 * 512];
__device__ __nv_bfloat16 g_Wh[2048 * 512];
__device__ __nv_bfloat16 g_Wf[128 * 512];
__device__ float g_pb[2048];
__device__ __nv_bfloat16 g_xg[(size_t)MROWS * 2048];        // 540MB xg bf16
__device__ __nv_bfloat16 g_hb[(size_t)TSTEPS * BPAD * HID]; // 134MB bf16 h, t-indexed
__device__ unsigned g_bar[8 * 4 * 32];                      // [mgroup][kcluster], 128B apart

__device__ __forceinline__ float fast_sigmoid(float x) {
    return 1.f / (1.f + __expf(-x));
}
__device__ __forceinline__ float fast_tanh(float x) {
    float ax = fabsf(x);
    float e = __expf(-2.f * ax);
    float r = (1.f - e) / (1.f + e);
    return copysignf(r, x);
}

// ------------------------- init / prep -------------------------
__global__ void zero_state_kernel() {
    int idx = blockIdx.x * blockDim.x + threadIdx.x;
    if (idx < 8 * 4 * 32) g_bar[idx] = 0u;
}

__global__ void prep_xbf_kernel(const float* __restrict__ inp) {
    long long idx = (long long)blockIdx.x * blockDim.x + threadIdx.x;
    if (idx >= (long long)TSTEPS * BATCH * EMB) return;
    int e = (int)(idx & 511);
    long long r = idx >> 9;
    int b = (int)(r % BATCH);
    int t = (int)(r / BATCH);
    float v = inp[(size_t)b * TBSTRIDE + (size_t)t * EMB + e];
    g_xbf[((size_t)t * BPAD + b) * EMB + e] = __float2bfloat16_rn(v);
}

__global__ void zero_xbf_pad_kernel() {
    int idx = blockIdx.x * blockDim.x + threadIdx.x;
    int total = TSTEPS * 12 * EMB / 2;
    if (idx >= total) return;
    int per_t = 12 * EMB / 2;
    int t = idx / per_t;
    int o = idx - t * per_t;
    ((uint32_t*)(g_xbf + ((size_t)t * BPAD + BATCH) * EMB))[o] = 0u;
}

__global__ void prep_w_kernel(const float* __restrict__ Wih,
                              const float* __restrict__ Whh,
                              const float* __restrict__ bih,
                              const float* __restrict__ bhh,
                              const float* __restrict__ Wfc) {
    int idx = blockIdx.x * blockDim.x + threadIdx.x;
    int np = idx >> 10;
    int k  = idx & 1023;
    int j = np >> 2, gate = np & 3;
    int n = gate * HID + j;
    if (k < 512) g_Wx[np * 512 + k] = __float2bfloat16_rn(Wih[(size_t)n * EMB + k]);
    else         g_Wh[np * 512 + (k - 512)] = __float2bfloat16_rn(Whh[(size_t)n * HID + (k - 512)]);
    if (idx < 2048) {
        int jj = idx >> 2, gg = idx & 3;
        g_pb[idx] = bih[gg * HID + jj] + bhh[gg * HID + jj];
    }
    if (idx < 128 * 512) {
        int fn = idx >> 9, fk = idx & 511;
        g_Wf[idx] = (fn < NOUT) ? __float2bfloat16_rn(Wfc[(size_t)fn * 512 + fk])
                                : __float2bfloat16_rn(0.f);
    }
}

// ------------------------- mma / ldmatrix helpers -------------------------
__device__ __forceinline__ void mma_bf16(float* d, const uint32_t* a, const uint32_t* b) {
    asm volatile(
        "mma.sync.aligned.m16n8k16.row.col.f32.bf16.bf16.f32 "
        "{%0,%1,%2,%3}, {%4,%5,%6,%7}, {%8,%9}, {%0,%1,%2,%3};"
        : "+f"(d[0]), "+f"(d[1]), "+f"(d[2]), "+f"(d[3])
        : "r"(a[0]), "r"(a[1]), "r"(a[2]), "r"(a[3]), "r"(b[0]), "r"(b[1]));
}
__device__ __forceinline__ void ldsm_x4(uint32_t* r, uint32_t addr) {
    asm volatile("ldmatrix.sync.aligned.m8n8.x4.shared.b16 {%0,%1,%2,%3}, [%4];"
                 : "=r"(r[0]), "=r"(r[1]), "=r"(r[2]), "=r"(r[3]) : "r"(addr));
}

// -------------------------------------------------------------------------
// Big parallel GEMM: g_xg[131072][2048](bf16) = g_xbf @ g_Wx^T  (unchanged)
// -------------------------------------------------------------------------
#define XS2 72
#define XBUF (128 * XS2)
#define XG_SMEM (4 * XBUF * 2)       // 73728

__global__ __launch_bounds__(256) void xg_gemm_kernel() {
    extern __shared__ __nv_bfloat16 xsm[];
    __nv_bfloat16* As = xsm;
    __nv_bfloat16* Bs = xsm + 2 * XBUF;
    const int tid = threadIdx.x;
    const int lid = tid & 31, wid = tid >> 5;
    const int tg = lid & 3, gr = lid >> 2;
    const int mw = wid & 3, nw = wid >> 2;
    const size_t R0 = (size_t)blockIdx.y * 128;
    const int n0 = blockIdx.x * 128;

    float acc[2][8][4];
#pragma unroll
    for (int mf = 0; mf < 2; mf++)
#pragma unroll
        for (int nf = 0; nf < 8; nf++)
#pragma unroll
            for (int r = 0; r < 4; r++) acc[mf][nf][r] = 0.f;

    uint32_t aA[2][2], bB[2][4];
    {
        const uint32_t abase = (uint32_t)__cvta_generic_to_shared(As);
        const uint32_t bbase = (uint32_t)__cvta_generic_to_shared(Bs);
        const int arow = mw * 32 + (lid & 15);
        const int acol = (lid >> 4) << 3;
        const int brb = nw * 64 + ((lid >> 4) << 3) + (lid & 7);
        const int bcol = ((lid >> 3) & 1) << 3;
#pragma unroll
        for (int buf = 0; buf < 2; buf++) {
#pragma unroll
            for (int mf = 0; mf < 2; mf++)
                aA[buf][mf] = abase + (uint32_t)(buf * XBUF + (arow + mf * 16) * XS2 + acol) * 2;
#pragma unroll
            for (int p = 0; p < 4; p++)
                bB[buf][p] = bbase + (uint32_t)(buf * XBUF + (brb + p * 16) * XS2 + bcol) * 2;
        }
    }

    auto load_stage = [&](int s) {
        const int buf = s & 1;
        const int k0 = s * 64;
#pragma unroll
        for (int it = 0; it < 4; it++) {
            int idx = tid + 256 * it;
            int r = idx >> 3, ch = idx & 7;
            const __nv_bfloat16* src = g_xbf + (R0 + r) * EMB + k0 + ch * 8;
            uint32_t dst = (uint32_t)__cvta_generic_to_shared(&As[buf * XBUF + r * XS2 + ch * 8]);
            asm volatile("cp.async.cg.shared.global [%0], [%1], 16;" :: "r"(dst), "l"(src));
        }
#pragma unroll
        for (int it = 0; it < 4; it++) {
            int idx = tid + 256 * it;
            int r = idx >> 3, ch = idx & 7;
            const __nv_bfloat16* src = g_Wx + (size_t)(n0 + r) * 512 + k0 + ch * 8;
            uint32_t dst = (uint32_t)__cvta_generic_to_shared(&Bs[buf * XBUF + r * XS2 + ch * 8]);
            asm volatile("cp.async.cg.shared.global [%0], [%1], 16;" :: "r"(dst), "l"(src));
        }
        asm volatile("cp.async.commit_group;" ::: "memory");
    };

    load_stage(0);
#pragma unroll 1
    for (int s = 0; s < 8; s++) {
        if (s + 1 < 8) {
            load_stage(s + 1);
            asm volatile("cp.async.wait_group 1;" ::: "memory");
        } else {
            asm volatile("cp.async.wait_group 0;" ::: "memory");
        }
        __syncthreads();
        const int buf = s & 1;
#pragma unroll
        for (int kk = 0; kk < 4; kk++) {
            uint32_t a0[4], a1[4];
            ldsm_x4(a0, aA[buf][0] + kk * 32);
            ldsm_x4(a1, aA[buf][1] + kk * 32);
#pragma unroll
            for (int p = 0; p < 4; p++) {
                uint32_t bb[4];
                ldsm_x4(bb, bB[buf][p] + kk * 32);
                mma_bf16(acc[0][2 * p],     a0, bb);
                mma_bf16(acc[0][2 * p + 1], a0, bb + 2);
                mma_bf16(acc[1][2 * p],     a1, bb);
                mma_bf16(acc[1][2 * p + 1], a1, bb + 2);
            }
        }
        __syncthreads();
    }

    uint32_t* xg32 = (uint32_t*)g_xg;
#pragma unroll
    for (int mf = 0; mf < 2; mf++)
#pragma unroll
        for (int nf = 0; nf < 8; nf++) {
            size_t R = R0 + mw * 32 + mf * 16 + gr;
            int c = n0 + nw * 64 + nf * 8 + 2 * tg;
            __nv_bfloat162 lo = __float22bfloat162_rn(make_float2(acc[mf][nf][0], acc[mf][nf][1]));
            __nv_bfloat162 hi = __float22bfloat162_rn(make_float2(acc[mf][nf][2], acc[mf][nf][3]));
            xg32[R * 1024 + (c >> 1)]       = *(uint32_t*)&lo;
            xg32[(R + 8) * 1024 + (c >> 1)] = *(uint32_t*)&hi;
        }
}

// -------------------------------------------------------------------------
// Persistent LSTM: 256 CTAs (8 m-groups of 64 rows x 32 n-tiles), 2 CTAs/SM.
// Quarter-wise K-cluster flags: consumer spins per 128-col cluster, so
// producer skew overlaps with MMA of earlier quarters.
// -------------------------------------------------------------------------
#define ST 520
#define AST 136
#define ABUF (64 * AST * 2)                     // 17408 bytes
#define HS2 24
#define OFF_WH 0
#define OFF_A  (64 * ST * 2)                    // 66560
#define OFF_HS (OFF_A + 2 * ABUF)               // 101376
#define PERSIST_SMEM (OFF_HS + 64 * HS2 * 2)    // 104448

__global__ __launch_bounds__(256, 2) void lstm_persist_kernel() {
    extern __shared__ char sm[];
    __nv_bfloat16* Hsb = (__nv_bfloat16*)(sm + OFF_HS);

    const int tid = threadIdx.x;
    const int lid = tid & 31, wid = tid >> 5;
    const int tg = lid & 3, gr = lid >> 2;
    const int mw = wid & 1, nw = wid >> 1;      // 2 m-warps x 4 n-warps
    const int mblk = blockIdx.x;                // 8 m-groups
    const int m0 = mblk * 64;
    const int n0 = blockIdx.y * 64;
    const bool even = (tg & 1) == 0;

    // producer counter: cluster of this CTA's h columns (16 cols -> cluster y>>3)
    unsigned* my_bar = &g_bar[(mblk * 4 + ((int)blockIdx.y >> 3)) * 32];
    unsigned* bar0 = &g_bar[(mblk * 4) * 32];   // consumer: cluster q at bar0 + q*32

    // ---- Wh slice (64 rows x 512 bf16) resident ----
#pragma unroll
    for (int it = 0; it < 16; it++) {
        int idx = tid + 256 * it;
        int r = idx >> 6, ch = idx & 63;
        const __nv_bfloat16* src = g_Wh + (size_t)(n0 + r) * 512 + ch * 8;
        uint32_t dst = (uint32_t)__cvta_generic_to_shared(sm + OFF_WH + (r * ST + ch * 8) * 2);
        asm volatile("cp.async.cg.shared.global [%0], [%1], 16;" :: "r"(dst), "l"(src));
    }
    asm volatile("cp.async.commit_group;" ::: "memory");
    asm volatile("cp.async.wait_group 0;" ::: "memory");
    __syncthreads();

    uint32_t aaddr[2][2], baddr;
    {
        const uint32_t smbase = (uint32_t)__cvta_generic_to_shared(sm);
        const int arow = mw * 32 + (lid & 15);
        const int acol = (lid >> 4) << 3;
#pragma unroll
        for (int buf = 0; buf < 2; buf++)
#pragma unroll
            for (int mf = 0; mf < 2; mf++)
                aaddr[buf][mf] = smbase + OFF_A + buf * ABUF
                               + (uint32_t)((arow + mf * 16) * AST + acol) * 2;
        const int brow = nw * 16 + ((lid >> 4) << 3) + (lid & 7);
        const int bcol = ((lid >> 3) & 1) << 3;
        baddr = smbase + OFF_WH + (uint32_t)(brow * ST + bcol) * 2;
    }

    float4 pb4[2];
#pragma unroll
    for (int nf = 0; nf < 2; nf++) {
        int jc = nw * 4 + 2 * nf + (tg >> 1);
        pb4[nf] = *(const float4*)&g_pb[n0 + jc * 4];
    }

    float creg[2][2][2];
#pragma unroll
    for (int mf = 0; mf < 2; mf++)
#pragma unroll
        for (int nf = 0; nf < 2; nf++) { creg[mf][nf][0] = 0.f; creg[mf][nf][1] = 0.f; }

    const uint32_t* xg32 = (const uint32_t*)g_xg;
    const int colu = (n0 + nw * 16 + 2 * tg) >> 1;

    float acc[2][2][4];

    auto spin_q = [&](int q, unsigned target) {
        unsigned v;
        do {
            asm volatile("ld.acquire.gpu.global.u32 %0, [%1];"
                         : "=r"(v) : "l"(bar0 + q * 32) : "memory");
        } while (v < target);
    };

    auto load_q = [&](const __nv_bfloat16* hsrc, int q, int buf) {
#pragma unroll
        for (int it = 0; it < 4; it++) {
            int idx = tid + 256 * it;
            int r = idx >> 4, ch = idx & 15;
            const __nv_bfloat16* src = hsrc + (size_t)r * HID + q * 128 + ch * 8;
            uint32_t dst = (uint32_t)__cvta_generic_to_shared(
                sm + OFF_A + buf * ABUF + (r * AST + ch * 8) * 2);
            asm volatile("cp.async.cg.shared.global [%0], [%1], 16;" :: "r"(dst), "l"(src));
        }
        asm volatile("cp.async.commit_group;" ::: "memory");
    };

    auto mma_q = [&](int q, int buf) {
#pragma unroll
        for (int kkl = 0; kkl < 8; kkl++) {
            uint32_t a0[4], a1[4], bb[4];
            ldsm_x4(a0, aaddr[buf][0] + kkl * 32);
            ldsm_x4(a1, aaddr[buf][1] + kkl * 32);
            ldsm_x4(bb, baddr + (q * 8 + kkl) * 32);
            mma_bf16(acc[0][0], a0, bb);     mma_bf16(acc[0][1], a0, bb + 2);
            mma_bf16(acc[1][0], a1, bb);     mma_bf16(acc[1][1], a1, bb + 2);
        }
    };

#pragma unroll 1
    for (int t = 0; t < TSTEPS; t++) {
        // ---- xg prefetch (independent of flags) ----
        uint32_t xr[2][2][2];
        {
            const size_t rb = (size_t)t * BPAD + m0 + mw * 32 + gr;
#pragma unroll
            for (int mf = 0; mf < 2; mf++)
#pragma unroll
                for (int nf = 0; nf < 2; nf++) {
                    const size_t r0 = (rb + mf * 16) * 1024 + colu + nf * 4;
                    xr[mf][nf][0] = __ldg(xg32 + r0);
                    xr[mf][nf][1] = __ldg(xg32 + r0 + 8 * 1024);
                }
        }

#pragma unroll
        for (int mf = 0; mf < 2; mf++)
#pragma unroll
            for (int nf = 0; nf < 2; nf++)
#pragma unroll
                for (int r = 0; r < 4; r++) acc[mf][nf][r] = 0.f;

        if (t > 0) {
            const unsigned target = 8u * (unsigned)t;   // 8 producers per cluster
            const __nv_bfloat16* hsrc = g_hb + ((size_t)(t - 1) * BPAD + m0) * HID;

            spin_q(0, target);
            load_q(hsrc, 0, 0);
            spin_q(1, target);
            load_q(hsrc, 1, 1);
            asm volatile("cp.async.wait_group 1;" ::: "memory");
            __syncthreads();
            mma_q(0, 0);
            __syncthreads();
            spin_q(2, target);
            load_q(hsrc, 2, 0);
            asm volatile("cp.async.wait_group 1;" ::: "memory");
            __syncthreads();
            mma_q(1, 1);
            __syncthreads();
            spin_q(3, target);
            load_q(hsrc, 3, 1);
            asm volatile("cp.async.wait_group 1;" ::: "memory");
            __syncthreads();
            mma_q(2, 0);
            asm volatile("cp.async.wait_group 0;" ::: "memory");
            __syncthreads();
            mma_q(3, 1);
        }

        // ---- epilogue: + xg, + bias, gate exchange, cell update -> Hsb ----
#pragma unroll
        for (int mf = 0; mf < 2; mf++) {
            const int row = mw * 32 + mf * 16 + gr;
#pragma unroll
            for (int nf = 0; nf < 2; nf++) {
                float2 x0 = __bfloat1622float2(*(__nv_bfloat162*)&xr[mf][nf][0]);
                float2 x1 = __bfloat1622float2(*(__nv_bfloat162*)&xr[mf][nf][1]);
                float b0 = even ? pb4[nf].x : pb4[nf].z;
                float b1 = even ? pb4[nf].y : pb4[nf].w;
                float v0 = acc[mf][nf][0] + x0.x + b0;
                float v1 = acc[mf][nf][1] + x0.y + b1;
                float v2 = acc[mf][nf][2] + x1.x + b0;
                float v3 = acc[mf][nf][3] + x1.y + b1;
                float s0 = __shfl_xor_sync(0xffffffffu, v0, 1);
                float s1 = __shfl_xor_sync(0xffffffffu, v1, 1);
                float s2 = __shfl_xor_sync(0xffffffffu, v2, 1);
                float s3 = __shfl_xor_sync(0xffffffffu, v3, 1);
                if (even) {
                    const int jc = nw * 4 + 2 * nf + (tg >> 1);
                    float ig0 = fast_sigmoid(v0), fg0 = fast_sigmoid(v1);
                    float gt0 = fast_tanh(s0),    ot0 = fast_sigmoid(s1);
                    float c0 = fg0 * creg[mf][nf][0] + ig0 * gt0;
                    creg[mf][nf][0] = c0;
                    Hsb[row * HS2 + jc] = __float2bfloat16_rn(ot0 * fast_tanh(c0));
                    float ig1 = fast_sigmoid(v2), fg1 = fast_sigmoid(v3);
                    float gt1 = fast_tanh(s2),    ot1 = fast_sigmoid(s3);
                    float c1 = fg1 * creg[mf][nf][1] + ig1 * gt1;
                    creg[mf][nf][1] = c1;
                    Hsb[(row + 8) * HS2 + jc] = __float2bfloat16_rn(ot1 * fast_tanh(c1));
                }
            }
        }
        __syncthreads();

        // ---- coalesced flush: 128 x 16B stores (64 rows x 16 cols) ----
        if (tid < 128) {
            const int row = tid >> 1, half = tid & 1;
            uint4 v = *(uint4*)&Hsb[row * HS2 + half * 8];
            *(uint4*)(g_hb + (size_t)t * BPAD * HID +
                      (size_t)(m0 + row) * HID + blockIdx.y * 16 + half * 8) = v;
        }
        __syncthreads();
        if (tid == 0) {
            asm volatile("red.release.gpu.global.add.u32 [%0], 1;"
                         :: "l"(my_bar) : "memory");
        }
    }
}

// -------------------------------------------------------------------------
// FC (bf16 mma): out[b][t][o] = sigmoid(g_hb[t][b] . W_fc[o] + b_fc[o])
// -------------------------------------------------------------------------
#define XA_STRIDE 40
__global__ __launch_bounds__(256) void fc_gemm_kernel(
    const float* __restrict__ bfc,
    float* __restrict__ out)
{
    __shared__ __nv_bfloat16 As[2][128 * XA_STRIDE];
    __shared__ __nv_bfloat16 Bs[2][128 * XA_STRIDE];
    const int tid = threadIdx.x;
    const int lid = tid & 31, wid = tid >> 5;
    const int tg = lid & 3, gr = lid >> 2;
    const int mw = wid & 3, nw = wid >> 2;
    const size_t R0 = (size_t)blockIdx.x * 128;

    float acc[2][8][4];
#pragma unroll
    for (int mf = 0; mf < 2; mf++)
#pragma unroll
        for (int nf = 0; nf < 8; nf++)
#pragma unroll
            for (int r = 0; r < 4; r++) acc[mf][nf][r] = 0.f;

    auto load_stage = [&](int s) {
        const int buf = s & 1;
        const int k0 = s * 32;
#pragma unroll
        for (int it = 0; it < 2; it++) {
            int idx = tid + 256 * it;
            int r = idx >> 2, ch = idx & 3;
            const __nv_bfloat16* src = g_hb + (R0 + r) * HID + k0 + ch * 8;
            uint32_t dst = (uint32_t)__cvta_generic_to_shared(&As[buf][r * XA_STRIDE + ch * 8]);
            asm volatile("cp.async.cg.shared.global [%0], [%1], 16;" :: "r"(dst), "l"(src));
        }
#pragma unroll
        for (int it = 0; it < 2; it++) {
            int idx = tid + 256 * it;
            int r = idx >> 2, ch = idx & 3;
            const __nv_bfloat16* src = g_Wf + (size_t)r * 512 + k0 + ch * 8;
            uint32_t dst = (uint32_t)__cvta_generic_to_shared(&Bs[buf][r * XA_STRIDE + ch * 8]);
            asm volatile("cp.async.cg.shared.global [%0], [%1], 16;" :: "r"(dst), "l"(src));
        }
        asm volatile("cp.async.commit_group;" ::: "memory");
    };

    load_stage(0);
#pragma unroll 1
    for (int s = 0; s < 16; s++) {
        if (s + 1 < 16) {
            load_stage(s + 1);
            asm volatile("cp.async.wait_group 1;" ::: "memory");
        } else {
            asm volatile("cp.async.wait_group 0;" ::: "memory");
        }
        __syncthreads();
        const int buf = s & 1;
        const __nv_bfloat16* Ab = &As[buf][(mw * 32) * XA_STRIDE];
        const __nv_bfloat16* Bb = &Bs[buf][(nw * 64) * XA_STRIDE];
#pragma unroll
        for (int ks = 0; ks < 2; ks++) {
            const int k = ks * 16 + tg * 2;
            uint32_t a[2][4];
#pragma unroll
            for (int mf = 0; mf < 2; mf++) {
                const __nv_bfloat16* p = Ab + (mf * 16 + gr) * XA_STRIDE + k;
                a[mf][0] = *(const uint32_t*)p;
                a[mf][1] = *(const uint32_t*)(p + 8 * XA_STRIDE);
                a[mf][2] = *(const uint32_t*)(p + 8);
                a[mf][3] = *(const uint32_t*)(p + 8 * XA_STRIDE + 8);
            }
#pragma unroll
            for (int nf = 0; nf < 8; nf++) {
                const __nv_bfloat16* p = Bb + (nf * 8 + gr) * XA_STRIDE + k;
                uint32_t b[2];
                b[0] = *(const uint32_t*)p;
                b[1] = *(const uint32_t*)(p + 8);
#pragma unroll
                for (int mf = 0; mf < 2; mf++) mma_bf16(acc[mf][nf], a[mf], b);
            }
        }
        __syncthreads();
    }

#pragma unroll
    for (int mf = 0; mf < 2; mf++)
#pragma unroll
        for (int nf = 0; nf < 8; nf++) {
            const int c = nw * 64 + nf * 8 + 2 * tg;
            if (c >= NOUT) continue;
#pragma unroll
            for (int half = 0; half < 2; half++) {
                size_t R = R0 + mw * 32 + mf * 16 + gr + half * 8;
                int t = (int)(R >> 9);
                int b = (int)(R & 511);
                if (b < BATCH) {
                    float* dst = out + ((size_t)b * TSTEPS + t) * NOUT + c;
                    dst[0] = fast_sigmoid(acc[mf][nf][half * 2 + 0] + bfc[c]);
                    dst[1] = fast_sigmoid(acc[mf][nf][half * 2 + 1] + bfc[c + 1]);
                }
            }
        }
}

// -------------------------------------------------------------------------
extern "C" void kernel_launch(void* const* d_in, const int* in_sizes, int n_in,
                              void* d_out, int out_size) {
    const float* inp  = (const float*)d_in[0];
    const float* Wih  = (const float*)d_in[1];
    const float* Whh  = (const float*)d_in[2];
    const float* bih  = (const float*)d_in[3];
    const float* bhh  = (const float*)d_in[4];
    const float* Wfc  = (const float*)d_in[5];
    const float* bfc  = (const float*)d_in[6];
    float* out = (float*)d_out;

    cudaFuncSetAttribute(lstm_persist_kernel,
                         cudaFuncAttributeMaxDynamicSharedMemorySize, PERSIST_SMEM);
    cudaFuncSetAttribute(xg_gemm_kernel,
                         cudaFuncAttributeMaxDynamicSharedMemorySize, XG_SMEM);

    zero_state_kernel<<<4, 256>>>();
    {
        long long total = (long long)TSTEPS * BATCH * EMB;
        int blocks = (int)((total + 255) / 256);
        prep_xbf_kernel<<<blocks, 256>>>(inp);
    }
    zero_xbf_pad_kernel<<<(TSTEPS * 12 * EMB / 2 + 255) / 256, 256>>>();
    prep_w_kernel<<<(2048 * 1024) / 256, 256>>>(Wih, Whh, bih, bhh, Wfc);

    xg_gemm_kernel<<<dim3(16, MROWS / 128), 256, XG_SMEM>>>();

    lstm_persist_kernel<<<dim3(8, 32), 256, PERSIST_SMEM>>>();

    fc_gemm_kernel<<<1024, 256>>>(bfc, out);
}